// round 1
// baseline (speedup 1.0000x reference)
#include <cuda_runtime.h>

// Causal scaled-dot-product attention, B=2 H=16 S=2048 D=64, fp32.
// Flash-attention SIMT baseline: 64-query tile per CTA, 64-key tiles,
// online softmax, 4x4 register tiles on a 16x16 thread grid.

namespace {

constexpr int S_LEN = 2048;
constexpr int DH    = 64;
constexpr int BM    = 64;   // queries per CTA
constexpr int BN    = 64;   // keys per tile
constexpr int TSTR  = 68;   // padded stride for transposed Q/K tiles (16B aligned, spreads banks)
constexpr int NTHREADS = 256;

__global__ __launch_bounds__(NTHREADS)
void fa_kernel(const float* __restrict__ Q, const float* __restrict__ K,
               const float* __restrict__ V, float* __restrict__ Out) {
    extern __shared__ float smem[];
    float* sQt = smem;                   // [DH][TSTR]  Q^T tile
    float* sKt = sQt + DH * TSTR;        // [DH][TSTR]  K^T tile
    float* sV  = sKt + DH * TSTR;        // [BN][DH]    V tile (row major)
    float* sP  = sV + BN * DH;           // [BM][BN]    probabilities

    const int tid = threadIdx.x;
    const int tx  = tid & 15;            // -> key cols (gemm1) / dims (gemm2)
    const int ty  = tid >> 4;            // -> query rows
    const int qb  = (int)gridDim.x - 1 - (int)blockIdx.x;  // heavy tiles first
    const int bh  = blockIdx.y;
    const int qbase = qb * BM;

    const size_t hoff = (size_t)bh * S_LEN * DH;
    const float* Qp = Q + hoff;
    const float* Kp = K + hoff;
    const float* Vp = V + hoff;
    float* Op = Out + hoff;

    // ---- load Q tile, transposed into smem ----
    {
        const int d4 = (tid & 15) * 4;
        #pragma unroll
        for (int r = 0; r < 4; r++) {
            const int row = (tid >> 4) + 16 * r;
            float4 qv = *reinterpret_cast<const float4*>(
                Qp + (size_t)(qbase + row) * DH + d4);
            sQt[(d4 + 0) * TSTR + row] = qv.x;
            sQt[(d4 + 1) * TSTR + row] = qv.y;
            sQt[(d4 + 2) * TSTR + row] = qv.z;
            sQt[(d4 + 3) * TSTR + row] = qv.w;
        }
    }

    float acc[4][4];
    #pragma unroll
    for (int i = 0; i < 4; i++)
        #pragma unroll
        for (int j = 0; j < 4; j++) acc[i][j] = 0.f;

    float m_i[4], l_i[4];
    #pragma unroll
    for (int i = 0; i < 4; i++) { m_i[i] = -1e30f; l_i[i] = 0.f; }

    for (int kb = 0; kb <= qb; kb++) {
        __syncthreads();  // guards sKt/sV/sP reuse from previous iteration

        // ---- load K (transposed) and V tiles ----
        {
            const int d4 = (tid & 15) * 4;
            #pragma unroll
            for (int r = 0; r < 4; r++) {
                const int row = (tid >> 4) + 16 * r;
                const size_t g = (size_t)(kb * BN + row) * DH + d4;
                float4 kv = *reinterpret_cast<const float4*>(Kp + g);
                sKt[(d4 + 0) * TSTR + row] = kv.x;
                sKt[(d4 + 1) * TSTR + row] = kv.y;
                sKt[(d4 + 2) * TSTR + row] = kv.z;
                sKt[(d4 + 3) * TSTR + row] = kv.w;
                float4 vv = *reinterpret_cast<const float4*>(Vp + g);
                *reinterpret_cast<float4*>(sV + row * DH + d4) = vv;
            }
        }
        __syncthreads();

        // ---- GEMM1: S = Q @ K^T (4x4 per thread) ----
        float sc[4][4];
        #pragma unroll
        for (int i = 0; i < 4; i++)
            #pragma unroll
            for (int j = 0; j < 4; j++) sc[i][j] = 0.f;

        #pragma unroll 8
        for (int d = 0; d < DH; d++) {
            float4 qv = *reinterpret_cast<const float4*>(sQt + d * TSTR + 4 * ty);
            float4 kv = *reinterpret_cast<const float4*>(sKt + d * TSTR + 4 * tx);
            const float qr[4] = {qv.x, qv.y, qv.z, qv.w};
            const float kr[4] = {kv.x, kv.y, kv.z, kv.w};
            #pragma unroll
            for (int i = 0; i < 4; i++)
                #pragma unroll
                for (int j = 0; j < 4; j++)
                    sc[i][j] += qr[i] * kr[j];
        }

        // ---- scale + causal mask (only diagonal tile needs elementwise mask) ----
        const float scale = 0.125f;  // 1/sqrt(64)
        if (kb == qb) {
            #pragma unroll
            for (int i = 0; i < 4; i++)
                #pragma unroll
                for (int j = 0; j < 4; j++)
                    sc[i][j] = (4 * tx + j > 4 * ty + i) ? -1e30f : sc[i][j] * scale;
        } else {
            #pragma unroll
            for (int i = 0; i < 4; i++)
                #pragma unroll
                for (int j = 0; j < 4; j++)
                    sc[i][j] *= scale;
        }

        // ---- online softmax (row stats across 16 lanes of each half-warp) ----
        #pragma unroll
        for (int i = 0; i < 4; i++) {
            float rmx = fmaxf(fmaxf(sc[i][0], sc[i][1]), fmaxf(sc[i][2], sc[i][3]));
            #pragma unroll
            for (int off = 8; off >= 1; off >>= 1)
                rmx = fmaxf(rmx, __shfl_xor_sync(0xffffffffu, rmx, off));

            const float mnew  = fmaxf(m_i[i], rmx);
            const float alpha = __expf(m_i[i] - mnew);
            m_i[i] = mnew;

            float rs = 0.f;
            #pragma unroll
            for (int j = 0; j < 4; j++) {
                sc[i][j] = __expf(sc[i][j] - mnew);
                rs += sc[i][j];
            }
            #pragma unroll
            for (int off = 8; off >= 1; off >>= 1)
                rs += __shfl_xor_sync(0xffffffffu, rs, off);

            l_i[i] = l_i[i] * alpha + rs;
            #pragma unroll
            for (int j = 0; j < 4; j++) acc[i][j] *= alpha;

            float4 pv = make_float4(sc[i][0], sc[i][1], sc[i][2], sc[i][3]);
            *reinterpret_cast<float4*>(sP + (4 * ty + i) * BN + 4 * tx) = pv;
        }
        __syncthreads();

        // ---- GEMM2: acc += P @ V (4x4 per thread; i->q rows, j->dims) ----
        #pragma unroll 4
        for (int kk = 0; kk < BN; kk += 4) {
            float4 pv[4], vv[4];
            #pragma unroll
            for (int i = 0; i < 4; i++)
                pv[i] = *reinterpret_cast<const float4*>(sP + (4 * ty + i) * BN + kk);
            #pragma unroll
            for (int t = 0; t < 4; t++)
                vv[t] = *reinterpret_cast<const float4*>(sV + (kk + t) * DH + 4 * tx);
            #pragma unroll
            for (int i = 0; i < 4; i++) {
                const float pr[4] = {pv[i].x, pv[i].y, pv[i].z, pv[i].w};
                #pragma unroll
                for (int t = 0; t < 4; t++) {
                    acc[i][0] += pr[t] * vv[t].x;
                    acc[i][1] += pr[t] * vv[t].y;
                    acc[i][2] += pr[t] * vv[t].z;
                    acc[i][3] += pr[t] * vv[t].w;
                }
            }
        }
    }

    // ---- epilogue: normalize and store ----
    #pragma unroll
    for (int i = 0; i < 4; i++) {
        const float inv = 1.0f / l_i[i];
        float4 o = make_float4(acc[i][0] * inv, acc[i][1] * inv,
                               acc[i][2] * inv, acc[i][3] * inv);
        *reinterpret_cast<float4*>(
            Op + (size_t)(qbase + 4 * ty + i) * DH + 4 * tx) = o;
    }
}

constexpr int SMEM_BYTES = (2 * DH * TSTR + BN * DH + BM * BN) * (int)sizeof(float);

}  // namespace

extern "C" void kernel_launch(void* const* d_in, const int* in_sizes, int n_in,
                              void* d_out, int out_size) {
    (void)in_sizes; (void)n_in; (void)out_size;
    const float* q = (const float*)d_in[0];
    const float* k = (const float*)d_in[1];
    const float* v = (const float*)d_in[2];
    // d_in[3] is the boolean tril mask; causality is implemented analytically.
    float* o = (float*)d_out;

    cudaFuncSetAttribute(fa_kernel, cudaFuncAttributeMaxDynamicSharedMemorySize,
                         SMEM_BYTES);
    dim3 grid(S_LEN / BM, 2 * 16);  // (q tiles, B*H)
    fa_kernel<<<grid, NTHREADS, SMEM_BYTES>>>(q, k, v, o);
}